// round 2
// baseline (speedup 1.0000x reference)
#include <cuda_runtime.h>
#include <math.h>

#define BB   64
#define NN   4096
#define DD   64
#define HH   256
#define SS   1024
#define TOT  49152   // 3 * D * H

// scratch: raw then normalized hypernet weights per batch
__device__ float g_params[BB * (size_t)TOT];

// ---------------- packed f32x2 helpers ----------------
__device__ __forceinline__ unsigned long long splat2(float a) {
    unsigned long long r;
    asm("mov.b64 %0, {%1, %1};" : "=l"(r) : "f"(a));
    return r;
}
__device__ __forceinline__ unsigned long long ffma2(unsigned long long a,
                                                    unsigned long long b,
                                                    unsigned long long c) {
    unsigned long long d;
    asm("fma.rn.f32x2 %0, %1, %2, %3;" : "=l"(d) : "l"(a), "l"(b), "l"(c));
    return d;
}
__device__ __forceinline__ float2 unpk(unsigned long long v) {
    float2 f;
    asm("mov.b64 {%0, %1}, %2;" : "=f"(f.x), "=f"(f.y) : "l"(v));
    return f;
}

// ---------------- kernel 1: hypernet GEMM ----------------
// mlp[b][n] = sum_k s[b][k] * W[k][n] + bias[n]
// M=64 (whole), block N-tile=128, K-tile=16. 256 threads: tx(0..31)->4 cols, ty(0..7)->8 rows.
__global__ __launch_bounds__(256) void k1_hypernet(const float* __restrict__ s,
                                                   const float* __restrict__ W,
                                                   const float* __restrict__ bias) {
    __shared__ float sA[16][64];    // [k][m]
    __shared__ float sB[16][128];   // [k][n]
    const int n0  = blockIdx.x * 128;
    const int tid = threadIdx.x;
    const int tx  = tid & 31, ty = tid >> 5;
    const int c0  = tx * 4, r0 = ty * 8;

    unsigned long long acc[8][2];
    #pragma unroll
    for (int i = 0; i < 8; i++) { acc[i][0] = 0ull; acc[i][1] = 0ull; }

    for (int k0 = 0; k0 < SS; k0 += 16) {
        // A chunk: 64 rows x 16 k
        {
            int m = tid >> 2, kk = (tid & 3) * 4;
            float4 a4 = *(const float4*)(s + (size_t)m * SS + k0 + kk);
            sA[kk + 0][m] = a4.x; sA[kk + 1][m] = a4.y;
            sA[kk + 2][m] = a4.z; sA[kk + 3][m] = a4.w;
        }
        // B chunk: 16 k x 128 n
        #pragma unroll
        for (int t = 0; t < 2; t++) {
            int idx = t * 256 + tid;
            int kk = idx >> 5, c4 = (idx & 31) * 4;
            *(float4*)(&sB[kk][c4]) =
                *(const float4*)(W + (size_t)(k0 + kk) * TOT + n0 + c4);
        }
        __syncthreads();
        #pragma unroll
        for (int kk = 0; kk < 16; kk++) {
            ulonglong2 bp = *(const ulonglong2*)(&sB[kk][c0]);   // 2 col-pairs
            float4 a0 = *(const float4*)(&sA[kk][r0]);
            float4 a1 = *(const float4*)(&sA[kk][r0 + 4]);
            unsigned long long s0 = splat2(a0.x), s1 = splat2(a0.y),
                               s2 = splat2(a0.z), s3 = splat2(a0.w),
                               s4 = splat2(a1.x), s5 = splat2(a1.y),
                               s6 = splat2(a1.z), s7 = splat2(a1.w);
            acc[0][0] = ffma2(s0, bp.x, acc[0][0]); acc[0][1] = ffma2(s0, bp.y, acc[0][1]);
            acc[1][0] = ffma2(s1, bp.x, acc[1][0]); acc[1][1] = ffma2(s1, bp.y, acc[1][1]);
            acc[2][0] = ffma2(s2, bp.x, acc[2][0]); acc[2][1] = ffma2(s2, bp.y, acc[2][1]);
            acc[3][0] = ffma2(s3, bp.x, acc[3][0]); acc[3][1] = ffma2(s3, bp.y, acc[3][1]);
            acc[4][0] = ffma2(s4, bp.x, acc[4][0]); acc[4][1] = ffma2(s4, bp.y, acc[4][1]);
            acc[5][0] = ffma2(s5, bp.x, acc[5][0]); acc[5][1] = ffma2(s5, bp.y, acc[5][1]);
            acc[6][0] = ffma2(s6, bp.x, acc[6][0]); acc[6][1] = ffma2(s6, bp.y, acc[6][1]);
            acc[7][0] = ffma2(s7, bp.x, acc[7][0]); acc[7][1] = ffma2(s7, bp.y, acc[7][1]);
        }
        __syncthreads();
    }
    float4 bv = *(const float4*)(bias + n0 + c0);
    #pragma unroll
    for (int i = 0; i < 8; i++) {
        float2 p0 = unpk(acc[i][0]), p1 = unpk(acc[i][1]);
        float4 o = make_float4(p0.x + bv.x, p0.y + bv.y, p1.x + bv.z, p1.y + bv.w);
        *(float4*)(g_params + (size_t)(r0 + i) * TOT + n0 + c0) = o;
    }
}

// ---------------- kernel 2: in-place L2 normalization ----------------
__global__ __launch_bounds__(256) void k2_normalize() {
    const int b   = blockIdx.x;
    const int tid = threadIdx.x;
    float* P = g_params + (size_t)b * TOT;

    // fc1 gate + value: [D][H] layout, norm over d (column h = tid)
    #pragma unroll
    for (int m = 0; m < 2; m++) {
        float* base = P + m * (DD * HH);
        float ss = 0.f;
        #pragma unroll 8
        for (int d = 0; d < DD; d++) { float v = base[d * HH + tid]; ss += v * v; }
        float inv = 1.f / fmaxf(sqrtf(ss), 1e-12f);
        #pragma unroll 8
        for (int d = 0; d < DD; d++) base[d * HH + tid] *= inv;
    }
    // fc2: [H][D] layout, norm over h (column d)
    __shared__ float part[4][64];
    __shared__ float invf[64];
    {
        float* base = P + 2 * (DD * HH);
        int dd = tid & 63, q = tid >> 6;
        float ss = 0.f;
        #pragma unroll 8
        for (int h = q * 64; h < q * 64 + 64; h++) { float v = base[h * DD + dd]; ss += v * v; }
        part[q][dd] = ss;
        __syncthreads();
        if (tid < 64) {
            float t = part[0][tid] + part[1][tid] + part[2][tid] + part[3][tid];
            invf[tid] = 1.f / fmaxf(sqrtf(t), 1e-12f);
        }
        __syncthreads();
        for (int i = tid; i < HH * DD; i += 256) base[i] *= invf[i & 63];
    }
}

// ---------------- kernel 3: fused RMSNorm + GLU MLP + residual ----------------
// grid (16, 64): blockIdx.y = batch, blockIdx.x -> 256 rows. 8 warps cooperate on
// groups of 8 rows. Weights resident in smem (fp32, 192 KB).
#define SMEM3_FLOATS (3 * DD * HH + DD * 8 + HH * 8 + 8 * 512)
#define SMEM3_BYTES  (SMEM3_FLOATS * 4)

__global__ __launch_bounds__(256) void k3_main(const float* __restrict__ x,
                                               const float* __restrict__ scale,
                                               float* __restrict__ out) {
    extern __shared__ float sm[];
    float* sWg  = sm;                  // [64][256]
    float* sWv  = sWg + DD * HH;       // [64][256]
    float* sWf  = sWv + DD * HH;       // [256][64]
    float* xT   = sWf + HH * DD;       // [d][8]
    float* hT   = xT + DD * 8;         // [h][8]
    float* pbuf = hT + HH * 8;         // [8][512]

    const int b    = blockIdx.y;
    const int nb0  = blockIdx.x * 256;
    const int tid  = threadIdx.x;
    const int w    = tid >> 5, lane = tid & 31;

    // preload normalized weights for this batch
    const float* P = g_params + (size_t)b * TOT;
    #pragma unroll 8
    for (int i = tid; i < TOT / 4; i += 256)
        ((float4*)sm)[i] = ((const float4*)P)[i];

    const float sc0 = scale[lane], sc1 = scale[lane + 32];
    __syncthreads();

    const float* xb = x + (size_t)b * NN * DD;

    for (int g = 0; g < 32; g++) {
        const int nb = nb0 + g * 8;

        // ---- phase A: RMSNorm, warp w handles row nb+w ----
        {
            const float* xr = xb + (size_t)(nb + w) * DD;
            float x0 = xr[lane], x1 = xr[lane + 32];
            float ssq = x0 * x0 + x1 * x1;
            #pragma unroll
            for (int o = 16; o > 0; o >>= 1) ssq += __shfl_xor_sync(0xffffffffu, ssq, o);
            float rr = rsqrtf(ssq * (1.0f / 64.0f) + 1e-6f);
            xT[lane * 8 + w]        = x0 * rr * sc0;
            xT[(lane + 32) * 8 + w] = x1 * rr * sc1;
        }
        __syncthreads();

        // ---- phase B: fc1 gate/value for h = w*32+lane over 8 rows ----
        {
            const int h = (w << 5) + lane;
            unsigned long long ag[4] = {0,0,0,0}, av[4] = {0,0,0,0};
            #pragma unroll 8
            for (int d = 0; d < DD; d++) {
                unsigned long long wg = splat2(sWg[d * HH + h]);
                unsigned long long wv = splat2(sWv[d * HH + h]);
                ulonglong2 xa = *(const ulonglong2*)(xT + d * 8);      // rows 0-3
                ulonglong2 xc = *(const ulonglong2*)(xT + d * 8 + 4);  // rows 4-7
                ag[0] = ffma2(xa.x, wg, ag[0]); ag[1] = ffma2(xa.y, wg, ag[1]);
                ag[2] = ffma2(xc.x, wg, ag[2]); ag[3] = ffma2(xc.y, wg, ag[3]);
                av[0] = ffma2(xa.x, wv, av[0]); av[1] = ffma2(xa.y, wv, av[1]);
                av[2] = ffma2(xc.x, wv, av[2]); av[3] = ffma2(xc.y, wv, av[3]);
            }
            float hv[8];
            #pragma unroll
            for (int p = 0; p < 4; p++) {
                float2 gg = unpk(ag[p]); float2 vv = unpk(av[p]);
                float e0 = __expf(-gg.x), e1 = __expf(-gg.y);
                hv[2 * p]     = gg.x * __fdividef(1.f, 1.f + e0) * vv.x;
                hv[2 * p + 1] = gg.y * __fdividef(1.f, 1.f + e1) * vv.y;
            }
            float4* hp = (float4*)(hT + h * 8);
            hp[0] = make_float4(hv[0], hv[1], hv[2], hv[3]);
            hp[1] = make_float4(hv[4], hv[5], hv[6], hv[7]);
        }
        __syncthreads();

        // ---- phase C: fc2 partials, warp w sums h in [w*32, w*32+32) ----
        {
            unsigned long long o0[4] = {0,0,0,0}, o1[4] = {0,0,0,0};
            const int hbase = w << 5;
            #pragma unroll 8
            for (int hh = 0; hh < 32; hh++) {
                const int h = hbase + hh;
                ulonglong2 ha = *(const ulonglong2*)(hT + h * 8);
                ulonglong2 hc = *(const ulonglong2*)(hT + h * 8 + 4);
                unsigned long long w0 = splat2(sWf[h * DD + lane]);
                unsigned long long w1 = splat2(sWf[h * DD + lane + 32]);
                o0[0] = ffma2(ha.x, w0, o0[0]); o0[1] = ffma2(ha.y, w0, o0[1]);
                o0[2] = ffma2(hc.x, w0, o0[2]); o0[3] = ffma2(hc.y, w0, o0[3]);
                o1[0] = ffma2(ha.x, w1, o1[0]); o1[1] = ffma2(ha.y, w1, o1[1]);
                o1[2] = ffma2(hc.x, w1, o1[2]); o1[3] = ffma2(hc.y, w1, o1[3]);
            }
            float* pb = pbuf + w * 512;
            #pragma unroll
            for (int p = 0; p < 4; p++) {
                float2 a = unpk(o0[p]); float2 c = unpk(o1[p]);
                pb[(2 * p) * 64 + lane]          = a.x;
                pb[(2 * p + 1) * 64 + lane]      = a.y;
                pb[(2 * p) * 64 + lane + 32]     = c.x;
                pb[(2 * p + 1) * 64 + lane + 32] = c.y;
            }
        }
        __syncthreads();

        // ---- reduce partials + residual + store ----
        {
            float* ob = out + ((size_t)b * NN + nb) * DD;
            const float* xr = xb + (size_t)nb * DD;
            #pragma unroll
            for (int t = 0; t < 2; t++) {
                int o = t * 256 + tid;
                float sum = 0.f;
                #pragma unroll
                for (int ww = 0; ww < 8; ww++) sum += pbuf[ww * 512 + o];
                ob[o] = sum + xr[o];
            }
        }
        __syncthreads();
    }
}

// ---------------- launch ----------------
extern "C" void kernel_launch(void* const* d_in, const int* in_sizes, int n_in,
                              void* d_out, int out_size) {
    const float* x     = (const float*)d_in[0];
    const float* s     = (const float*)d_in[1];
    const float* W     = (const float*)d_in[2];
    const float* bias  = (const float*)d_in[3];
    const float* scale = (const float*)d_in[4];
    float* out = (float*)d_out;

    k1_hypernet<<<dim3(TOT / 128), 256>>>(s, W, bias);
    k2_normalize<<<dim3(BB), 256>>>();

    cudaFuncSetAttribute(k3_main, cudaFuncAttributeMaxDynamicSharedMemorySize, SMEM3_BYTES);
    k3_main<<<dim3(NN / 256, BB), 256, SMEM3_BYTES>>>(x, scale, out);
}

// round 4
// speedup vs baseline: 2.4447x; 2.4447x over previous
#include <cuda_runtime.h>
#include <cstdint>
#include <math.h>

#define BB   64
#define NN   4096
#define DD   64
#define HH   256
#define SS   1024
#define TOT  49152   // 3 * D * H

// raw hypernet output (k1 -> k2)
__device__ float g_params[BB * (size_t)TOT];
// normalized tf32 weights in MMA-ready swizzled layout (k2 -> k3)
__device__ uint32_t g_wT[BB * (size_t)TOT];

// ======================= helpers =======================
__device__ __forceinline__ uint32_t f2tf(float f) {
    uint32_t r;
    asm("cvt.rna.tf32.f32 %0, %1;" : "=r"(r) : "f"(f));
    return r;
}

// D += A * B  (m16n8k8, tf32 inputs, fp32 accum)
__device__ __forceinline__ void mma_tf32(float* d, const uint32_t* a, uint32_t b0, uint32_t b1) {
    asm volatile("mma.sync.aligned.m16n8k8.row.col.f32.tf32.tf32.f32 "
                 "{%0,%1,%2,%3}, {%4,%5,%6,%7}, {%8,%9}, {%0,%1,%2,%3};"
                 : "+f"(d[0]), "+f"(d[1]), "+f"(d[2]), "+f"(d[3])
                 : "r"(a[0]), "r"(a[1]), "r"(a[2]), "r"(a[3]), "r"(b0), "r"(b1));
}

// ---------------- packed f32x2 helpers (k1) ----------------
__device__ __forceinline__ unsigned long long splat2(float a) {
    unsigned long long r; asm("mov.b64 %0, {%1, %1};" : "=l"(r) : "f"(a)); return r;
}
__device__ __forceinline__ unsigned long long ffma2(unsigned long long a, unsigned long long b,
                                                    unsigned long long c) {
    unsigned long long d;
    asm("fma.rn.f32x2 %0, %1, %2, %3;" : "=l"(d) : "l"(a), "l"(b), "l"(c));
    return d;
}
__device__ __forceinline__ float2 unpk(unsigned long long v) {
    float2 f; asm("mov.b64 {%0, %1}, %2;" : "=f"(f.x), "=f"(f.y) : "l"(v)); return f;
}

// ======================= kernel 1: hypernet GEMM (fp32, unchanged) =======================
__global__ __launch_bounds__(256) void k1_hypernet(const float* __restrict__ s,
                                                   const float* __restrict__ W,
                                                   const float* __restrict__ bias) {
    __shared__ float sA[16][64];
    __shared__ float sB[16][128];
    const int n0  = blockIdx.x * 128;
    const int tid = threadIdx.x;
    const int tx  = tid & 31, ty = tid >> 5;
    const int c0  = tx * 4, r0 = ty * 8;

    unsigned long long acc[8][2];
    #pragma unroll
    for (int i = 0; i < 8; i++) { acc[i][0] = 0ull; acc[i][1] = 0ull; }

    for (int k0 = 0; k0 < SS; k0 += 16) {
        {
            int m = tid >> 2, kk = (tid & 3) * 4;
            float4 a4 = *(const float4*)(s + (size_t)m * SS + k0 + kk);
            sA[kk + 0][m] = a4.x; sA[kk + 1][m] = a4.y;
            sA[kk + 2][m] = a4.z; sA[kk + 3][m] = a4.w;
        }
        #pragma unroll
        for (int t = 0; t < 2; t++) {
            int idx = t * 256 + tid;
            int kk = idx >> 5, c4 = (idx & 31) * 4;
            *(float4*)(&sB[kk][c4]) =
                *(const float4*)(W + (size_t)(k0 + kk) * TOT + n0 + c4);
        }
        __syncthreads();
        #pragma unroll
        for (int kk = 0; kk < 16; kk++) {
            ulonglong2 bp = *(const ulonglong2*)(&sB[kk][c0]);
            float4 a0 = *(const float4*)(&sA[kk][r0]);
            float4 a1 = *(const float4*)(&sA[kk][r0 + 4]);
            unsigned long long s0 = splat2(a0.x), s1 = splat2(a0.y),
                               s2 = splat2(a0.z), s3 = splat2(a0.w),
                               s4 = splat2(a1.x), s5 = splat2(a1.y),
                               s6 = splat2(a1.z), s7 = splat2(a1.w);
            acc[0][0] = ffma2(s0, bp.x, acc[0][0]); acc[0][1] = ffma2(s0, bp.y, acc[0][1]);
            acc[1][0] = ffma2(s1, bp.x, acc[1][0]); acc[1][1] = ffma2(s1, bp.y, acc[1][1]);
            acc[2][0] = ffma2(s2, bp.x, acc[2][0]); acc[2][1] = ffma2(s2, bp.y, acc[2][1]);
            acc[3][0] = ffma2(s3, bp.x, acc[3][0]); acc[3][1] = ffma2(s3, bp.y, acc[3][1]);
            acc[4][0] = ffma2(s4, bp.x, acc[4][0]); acc[4][1] = ffma2(s4, bp.y, acc[4][1]);
            acc[5][0] = ffma2(s5, bp.x, acc[5][0]); acc[5][1] = ffma2(s5, bp.y, acc[5][1]);
            acc[6][0] = ffma2(s6, bp.x, acc[6][0]); acc[6][1] = ffma2(s6, bp.y, acc[6][1]);
            acc[7][0] = ffma2(s7, bp.x, acc[7][0]); acc[7][1] = ffma2(s7, bp.y, acc[7][1]);
        }
        __syncthreads();
    }
    float4 bv = *(const float4*)(bias + n0 + c0);
    #pragma unroll
    for (int i = 0; i < 8; i++) {
        float2 p0 = unpk(acc[i][0]), p1 = unpk(acc[i][1]);
        float4 o = make_float4(p0.x + bv.x, p0.y + bv.y, p1.x + bv.z, p1.y + bv.w);
        *(float4*)(g_params + (size_t)(r0 + i) * TOT + n0 + c0) = o;
    }
}

// ======================= kernel 2: normalize -> tf32 swizzled MMA layout =======================
// Wg/Wv stored: word(k=d, n=h) = m*16384 + d*256 + (h ^ ((d&3)<<3))
// fc2   stored: word(k=h, n=d) = 32768  + h*64  + (d ^ ((h&3)<<3))
__global__ __launch_bounds__(256) void k2_normalize() {
    __shared__ float sinv[256];
    __shared__ float part[4][64];
    const int b = blockIdx.x, tid = threadIdx.x;
    const float* P = g_params + (size_t)b * TOT;
    uint32_t* dst = g_wT + (size_t)b * TOT;

    #pragma unroll
    for (int m = 0; m < 2; m++) {
        const float* src = P + m * 16384;
        {
            float ss = 0.f;
            #pragma unroll 8
            for (int d = 0; d < 64; d++) { float v = src[d * 256 + tid]; ss += v * v; }
            sinv[tid] = 1.f / fmaxf(sqrtf(ss), 1e-12f);
        }
        __syncthreads();
        for (int idx = tid; idx < 16384; idx += 256) {
            int d = idx >> 8, h = idx & 255;
            float v = src[idx] * sinv[h];
            dst[m * 16384 + d * 256 + (h ^ ((d & 3) << 3))] = f2tf(v);
        }
        __syncthreads();
    }
    {
        const float* src = P + 32768;
        int q = tid >> 6, dd = tid & 63;
        float ss = 0.f;
        #pragma unroll 8
        for (int h = q * 64; h < q * 64 + 64; h++) { float v = src[h * 64 + dd]; ss += v * v; }
        part[q][dd] = ss;
        __syncthreads();
        if (tid < 64)
            sinv[tid] = 1.f / fmaxf(sqrtf(part[0][tid] + part[1][tid] + part[2][tid] + part[3][tid]), 1e-12f);
        __syncthreads();
        for (int idx = tid; idx < 16384; idx += 256) {
            int h = idx >> 6, d = idx & 63;
            float v = src[idx] * sinv[d];
            dst[32768 + h * 64 + (d ^ ((h & 3) << 3))] = f2tf(v);
        }
    }
}

// ======================= kernel 3: mma.sync tf32 fused MLP =======================
// grid (8, 64): 512 rows per CTA, processed in 8 groups of 64.
// 8 warps: mw = w&3 (16-row m-tile), hw = w>>2 (H half of 128).
// smem: 49152 words weights (Wg|Wv|Wf) + 8448 words scratch [64][132]
#define K3_SMEM 230400

__global__ __launch_bounds__(256, 1) void k3_main(const float* __restrict__ x,
                                                  const float* __restrict__ scale,
                                                  float* __restrict__ out) {
    extern __shared__ uint32_t su[];
    float* hs = (float*)(su + 49152);       // scratch [64][132]
    const int tid = threadIdx.x, w = tid >> 5, lane = tid & 31;
    const int b = blockIdx.y;
    const int hw = w >> 2, mw = w & 3, m0 = mw * 16;
    const int r = lane >> 2, q = lane & 3;
    const int q8 = q << 3;
    const int hoff = hw * 68;

    // preload weights (already tf32 + swizzled)
    {
        const float4* wsrc = (const float4*)(g_wT + (size_t)b * TOT);
        float4* wdst = (float4*)su;
        #pragma unroll 8
        for (int i = tid; i < 12288; i += 256) wdst[i] = wsrc[i];
    }
    // per-thread scale regs (cols fixed per thread across groups)
    const int srow = tid >> 2, sqc = (tid & 3) * 16;
    float4 sc4[4];
    #pragma unroll
    for (int i = 0; i < 4; i++) sc4[i] = *(const float4*)(scale + sqc + 4 * i);
    __syncthreads();

    const uint32_t* Wg = su;
    const uint32_t* Wv = su + 16384;
    const uint32_t* Wf = su + 32768;

    for (int g = 0; g < 8; g++) {
        const int row0 = blockIdx.x * 512 + g * 64;

        // ---- stage RMSNorm'd xn into scratch (fp32, stride 132) ----
        {
            const float4* xr = (const float4*)(x + ((size_t)b * NN + row0 + srow) * DD + sqc);
            float4 v[4];
            float ssq = 0.f;
            #pragma unroll
            for (int i = 0; i < 4; i++) {
                v[i] = xr[i];
                ssq += v[i].x * v[i].x + v[i].y * v[i].y + v[i].z * v[i].z + v[i].w * v[i].w;
            }
            ssq += __shfl_xor_sync(0xffffffffu, ssq, 1);
            ssq += __shfl_xor_sync(0xffffffffu, ssq, 2);
            const float rr = rsqrtf(ssq * (1.0f / 64.0f) + 1e-6f);
            #pragma unroll
            for (int i = 0; i < 4; i++) {
                float4 o = make_float4(v[i].x * rr * sc4[i].x, v[i].y * rr * sc4[i].y,
                                       v[i].z * rr * sc4[i].z, v[i].w * rr * sc4[i].w);
                *(float4*)&hs[srow * 132 + sqc + 4 * i] = o;
            }
        }
        __syncthreads();

        // ---- load xn A-fragments into registers (held whole group) ----
        uint32_t xa[8][4];
        #pragma unroll
        for (int t = 0; t < 8; t++) {
            xa[t][0] = f2tf(hs[(m0 + r) * 132 + t * 8 + q]);
            xa[t][1] = f2tf(hs[(m0 + r + 8) * 132 + t * 8 + q]);
            xa[t][2] = f2tf(hs[(m0 + r) * 132 + t * 8 + q + 4]);
            xa[t][3] = f2tf(hs[(m0 + r + 8) * 132 + t * 8 + q + 4]);
        }
        __syncthreads();   // scratch now free -> h buffer

        float oacc[8][4];
        #pragma unroll
        for (int i = 0; i < 8; i++) { oacc[i][0] = oacc[i][1] = oacc[i][2] = oacc[i][3] = 0.f; }

        #pragma unroll
        for (int ch = 0; ch < 2; ch++) {
            const int nb = hw * 128 + ch * 64;

            // ---- MMA1: gate/value [16 x 64] over k=64 ----
            float ga[8][4], va[8][4];
            #pragma unroll
            for (int i = 0; i < 8; i++) {
                ga[i][0] = ga[i][1] = ga[i][2] = ga[i][3] = 0.f;
                va[i][0] = va[i][1] = va[i][2] = va[i][3] = 0.f;
            }
            #pragma unroll
            for (int kt = 0; kt < 8; kt++) {
                const uint32_t* g0 = Wg + (kt * 8 + q) * 256;
                const uint32_t* v0 = Wv + (kt * 8 + q) * 256;
                #pragma unroll
                for (int nt = 0; nt < 8; nt++) {
                    const int c = ((nb + nt * 8) ^ q8) + r;
                    mma_tf32(ga[nt], xa[kt], g0[c], g0[c + 1024]);
                    mma_tf32(va[nt], xa[kt], v0[c], v0[c + 1024]);
                }
            }

            // ---- h = silu(gate) * value -> warp-private scratch ----
            #pragma unroll
            for (int nt = 0; nt < 8; nt++) {
                float h0 = ga[nt][0] * __fdividef(1.f, 1.f + __expf(-ga[nt][0])) * va[nt][0];
                float h1 = ga[nt][1] * __fdividef(1.f, 1.f + __expf(-ga[nt][1])) * va[nt][1];
                float h2 = ga[nt][2] * __fdividef(1.f, 1.f + __expf(-ga[nt][2])) * va[nt][2];
                float h3 = ga[nt][3] * __fdividef(1.f, 1.f + __expf(-ga[nt][3])) * va[nt][3];
                *(float2*)&hs[(m0 + r) * 132 + hoff + nt * 8 + 2 * q]     = make_float2(h0, h1);
                *(float2*)&hs[(m0 + r + 8) * 132 + hoff + nt * 8 + 2 * q] = make_float2(h2, h3);
            }
            __syncwarp();

            // ---- MMA2: out += h[16 x 64] @ fc2 ----
            #pragma unroll
            for (int kt = 0; kt < 8; kt++) {
                uint32_t ha[4];
                ha[0] = f2tf(hs[(m0 + r) * 132 + hoff + kt * 8 + q]);
                ha[1] = f2tf(hs[(m0 + r + 8) * 132 + hoff + kt * 8 + q]);
                ha[2] = f2tf(hs[(m0 + r) * 132 + hoff + kt * 8 + q + 4]);
                ha[3] = f2tf(hs[(m0 + r + 8) * 132 + hoff + kt * 8 + q + 4]);
                const int kk = nb + kt * 8 + q;
                const uint32_t* f0 = Wf + kk * 64;
                #pragma unroll
                for (int nt = 0; nt < 8; nt++) {
                    const int c = ((nt * 8) ^ q8) + r;
                    mma_tf32(oacc[nt], ha, f0[c], f0[c + 256]);
                }
            }
            __syncwarp();
        }
        __syncthreads();   // everyone done with h scratch

        // ---- stash out partials (plain layout per hw region) ----
        #pragma unroll
        for (int nt = 0; nt < 8; nt++) {
            *(float2*)&hs[(m0 + r) * 132 + hoff + nt * 8 + 2 * q]     = make_float2(oacc[nt][0], oacc[nt][1]);
            *(float2*)&hs[(m0 + r + 8) * 132 + hoff + nt * 8 + 2 * q] = make_float2(oacc[nt][2], oacc[nt][3]);
        }
        __syncthreads();

        // ---- reduce halves + residual + store ----
        {
            const float4* xr = (const float4*)(x + ((size_t)b * NN + row0 + srow) * DD + sqc);
            float* orow = out + ((size_t)b * NN + row0 + srow) * DD + sqc;
            #pragma unroll
            for (int i = 0; i < 4; i++) {
                float4 a  = *(const float4*)&hs[srow * 132 + sqc + 4 * i];
                float4 c  = *(const float4*)&hs[srow * 132 + 68 + sqc + 4 * i];
                float4 xv = xr[i];
                float4 o = make_float4(a.x + c.x + xv.x, a.y + c.y + xv.y,
                                       a.z + c.z + xv.z, a.w + c.w + xv.w);
                *(float4*)(orow + 4 * i) = o;
            }
        }
        __syncthreads();
    }
}

// ======================= launch =======================
extern "C" void kernel_launch(void* const* d_in, const int* in_sizes, int n_in,
                              void* d_out, int out_size) {
    const float* x     = (const float*)d_in[0];
    const float* s     = (const float*)d_in[1];
    const float* W     = (const float*)d_in[2];
    const float* bias  = (const float*)d_in[3];
    const float* scale = (const float*)d_in[4];
    float* out = (float*)d_out;

    k1_hypernet<<<dim3(TOT / 128), 256>>>(s, W, bias);
    k2_normalize<<<dim3(BB), 256>>>();

    cudaFuncSetAttribute(k3_main, cudaFuncAttributeMaxDynamicSharedMemorySize, K3_SMEM);
    k3_main<<<dim3(8, BB), 256, K3_SMEM>>>(x, scale, out);
}

// round 5
// speedup vs baseline: 3.3463x; 1.3688x over previous
#include <cuda_runtime.h>
#include <cstdint>
#include <math.h>

#define BB   64
#define NN   4096
#define DD   64
#define HH   256
#define SS   1024
#define TOT  49152   // 3 * D * H

// raw hypernet output (k1 -> k2)
__device__ float g_params[BB * (size_t)TOT];
// normalized tf32 weights in MMA-ready swizzled layout (k2 -> k3)
__device__ uint32_t g_wT[BB * (size_t)TOT];

// ======================= helpers =======================
__device__ __forceinline__ uint32_t f2tf(float f) {
    uint32_t r;
    asm("cvt.rna.tf32.f32 %0, %1;" : "=r"(r) : "f"(f));
    return r;
}
__device__ __forceinline__ float tanha(float x) {
    float y;
    asm("tanh.approx.f32 %0, %1;" : "=f"(y) : "f"(x));
    return y;
}
__device__ __forceinline__ uint32_t smem_u32(const void* p) {
    uint32_t a;
    asm("{ .reg .u64 t; cvta.to.shared.u64 t, %1; cvt.u32.u64 %0, t; }" : "=r"(a) : "l"(p));
    return a;
}
__device__ __forceinline__ void cpa16(uint32_t dst, const void* src) {
    asm volatile("cp.async.cg.shared.global [%0], [%1], 16;" :: "r"(dst), "l"(src));
}
#define CP_COMMIT() asm volatile("cp.async.commit_group;" ::: "memory")
#define CP_WAIT1()  asm volatile("cp.async.wait_group 1;" ::: "memory")

// D += A * B  (m16n8k8, tf32 inputs, fp32 accum)
__device__ __forceinline__ void mma_tf32(float* d, const uint32_t* a, uint32_t b0, uint32_t b1) {
    asm volatile("mma.sync.aligned.m16n8k8.row.col.f32.tf32.tf32.f32 "
                 "{%0,%1,%2,%3}, {%4,%5,%6,%7}, {%8,%9}, {%0,%1,%2,%3};"
                 : "+f"(d[0]), "+f"(d[1]), "+f"(d[2]), "+f"(d[3])
                 : "r"(a[0]), "r"(a[1]), "r"(a[2]), "r"(a[3]), "r"(b0), "r"(b1));
}

// ======================= kernel 1: hypernet GEMM via mma.sync tf32 =======================
// C[64, 49152] = s[64,1024] @ W[1024,49152] + bias. CTA: N-tile 128, K-stage 32, 2-stage cp.async.
// 8 warps = 2(m) x 4(n), each m32 x n32. Smem: A [2][64][36] (LDS CF), B [2][32][136] (LDS CF).
#define K1_SMEM ((2 * 64 * 36 + 2 * 32 * 136) * 4)   // 53248 B

__global__ __launch_bounds__(256) void k1_mma(const float* __restrict__ s,
                                              const float* __restrict__ W,
                                              const float* __restrict__ bias) {
    extern __shared__ float sk[];
    float* sA = sk;              // 2 * 2304
    float* sB = sk + 4608;       // 2 * 4352
    const int n0  = blockIdx.x * 128;
    const int tid = threadIdx.x;
    const int w = tid >> 5, lane = tid & 31;
    const int r = lane >> 2, q = lane & 3;
    const int m0 = (w & 1) * 32, nw = (w >> 1) * 32;
    const uint32_t sbA = smem_u32(sA), sbB = smem_u32(sB);

    #define K1_LOAD(st, k0) do {                                                   \
        _Pragma("unroll")                                                          \
        for (int i = 0; i < 2; i++) {                                              \
            int c = tid + i * 256;                                                 \
            int row = c >> 3, cc = c & 7;                                          \
            cpa16(sbA + (uint32_t)((st) * 2304 + row * 36 + cc * 4) * 4,           \
                  s + (size_t)row * SS + (k0) + cc * 4);                           \
        }                                                                          \
        _Pragma("unroll")                                                          \
        for (int i = 0; i < 4; i++) {                                              \
            int c = tid + i * 256;                                                 \
            int row = c >> 5, cc = c & 31;                                         \
            cpa16(sbB + (uint32_t)((st) * 4352 + row * 136 + cc * 4) * 4,          \
                  W + (size_t)((k0) + row) * TOT + n0 + cc * 4);                   \
        }                                                                          \
    } while (0)

    float acc[2][4][4];
    #pragma unroll
    for (int mf = 0; mf < 2; mf++)
        #pragma unroll
        for (int nf = 0; nf < 4; nf++)
            acc[mf][nf][0] = acc[mf][nf][1] = acc[mf][nf][2] = acc[mf][nf][3] = 0.f;

    K1_LOAD(0, 0);  CP_COMMIT();
    K1_LOAD(1, 32); CP_COMMIT();

    for (int ks = 0; ks < 32; ks++) {
        CP_WAIT1();
        __syncthreads();
        const int st = ks & 1;
        const float* A  = sA + st * 2304;
        const float* Bp = sB + st * 4352;
        #pragma unroll
        for (int kk = 0; kk < 4; kk++) {
            uint32_t a[2][4];
            #pragma unroll
            for (int mf = 0; mf < 2; mf++) {
                const int mr = m0 + mf * 16 + r;
                a[mf][0] = __float_as_uint(A[mr * 36 + kk * 8 + q]);
                a[mf][1] = __float_as_uint(A[(mr + 8) * 36 + kk * 8 + q]);
                a[mf][2] = __float_as_uint(A[mr * 36 + kk * 8 + q + 4]);
                a[mf][3] = __float_as_uint(A[(mr + 8) * 36 + kk * 8 + q + 4]);
            }
            #pragma unroll
            for (int nf = 0; nf < 4; nf++) {
                const int cb = nw + nf * 8 + r;
                uint32_t b0 = __float_as_uint(Bp[(kk * 8 + q) * 136 + cb]);
                uint32_t b1 = __float_as_uint(Bp[(kk * 8 + q + 4) * 136 + cb]);
                mma_tf32(acc[0][nf], a[0], b0, b1);
                mma_tf32(acc[1][nf], a[1], b0, b1);
            }
        }
        __syncthreads();
        const int kn = (ks + 2) * 32;
        if (kn < SS) { K1_LOAD(st, kn); }
        CP_COMMIT();
    }

    #pragma unroll
    for (int nf = 0; nf < 4; nf++) {
        float2 bv = *(const float2*)(bias + n0 + nw + nf * 8 + 2 * q);
        #pragma unroll
        for (int mf = 0; mf < 2; mf++) {
            const int mr = m0 + mf * 16 + r;
            float* o0 = g_params + (size_t)mr * TOT + n0 + nw + nf * 8 + 2 * q;
            *(float2*)o0 = make_float2(acc[mf][nf][0] + bv.x, acc[mf][nf][1] + bv.y);
            float* o1 = g_params + (size_t)(mr + 8) * TOT + n0 + nw + nf * 8 + 2 * q;
            *(float2*)o1 = make_float2(acc[mf][nf][2] + bv.x, acc[mf][nf][3] + bv.y);
        }
    }
    #undef K1_LOAD
}

// ======================= kernel 2: normalize -> tf32 swizzled MMA layout =======================
// Wg/Wv stored: word(k=d, n=h) = m*16384 + d*256 + (h ^ ((d&3)<<3))
// fc2   stored: word(k=h, n=d) = 32768  + h*64  + (d ^ ((h&3)<<3))
__global__ __launch_bounds__(256) void k2_normalize() {
    __shared__ float sinv[256];
    __shared__ float part[4][64];
    const int b = blockIdx.x, tid = threadIdx.x;
    const float* P = g_params + (size_t)b * TOT;
    uint32_t* dst = g_wT + (size_t)b * TOT;

    #pragma unroll
    for (int m = 0; m < 2; m++) {
        const float* src = P + m * 16384;
        {
            float ss = 0.f;
            #pragma unroll 8
            for (int d = 0; d < 64; d++) { float v = src[d * 256 + tid]; ss += v * v; }
            sinv[tid] = 1.f / fmaxf(sqrtf(ss), 1e-12f);
        }
        __syncthreads();
        for (int idx = tid; idx < 16384; idx += 256) {
            int d = idx >> 8, h = idx & 255;
            float v = src[idx] * sinv[h];
            dst[m * 16384 + d * 256 + (h ^ ((d & 3) << 3))] = f2tf(v);
        }
        __syncthreads();
    }
    {
        const float* src = P + 32768;
        int q = tid >> 6, dd = tid & 63;
        float ss = 0.f;
        #pragma unroll 8
        for (int h = q * 64; h < q * 64 + 64; h++) { float v = src[h * 64 + dd]; ss += v * v; }
        part[q][dd] = ss;
        __syncthreads();
        if (tid < 64)
            sinv[tid] = 1.f / fmaxf(sqrtf(part[0][tid] + part[1][tid] + part[2][tid] + part[3][tid]), 1e-12f);
        __syncthreads();
        for (int idx = tid; idx < 16384; idx += 256) {
            int h = idx >> 6, d = idx & 63;
            float v = src[idx] * sinv[d];
            dst[32768 + h * 64 + (d ^ ((h & 3) << 3))] = f2tf(v);
        }
    }
}

// ======================= kernel 3: mma.sync tf32 fused MLP =======================
// grid (8, 64): 512 rows per CTA, processed in 8 groups of 64.
// 8 warps: mw = w&3 (16-row m-tile), hw = w>>2 (H half of 128).
// smem: 49152 words weights (Wg|Wv|Wf) + 8448 words scratch [64][132]
#define K3_SMEM 230400

__global__ __launch_bounds__(256, 1) void k3_main(const float* __restrict__ x,
                                                  const float* __restrict__ scale,
                                                  float* __restrict__ out) {
    extern __shared__ uint32_t su[];
    float* hs = (float*)(su + 49152);       // scratch [64][132]
    const int tid = threadIdx.x, w = tid >> 5, lane = tid & 31;
    const int b = blockIdx.y;
    const int hw = w >> 2, mw = w & 3, m0 = mw * 16;
    const int r = lane >> 2, q = lane & 3;
    const int q8 = q << 3;
    const int hoff = hw * 68;

    // preload weights (already tf32 + swizzled)
    {
        const float4* wsrc = (const float4*)(g_wT + (size_t)b * TOT);
        float4* wdst = (float4*)su;
        #pragma unroll 8
        for (int i = tid; i < 12288; i += 256) wdst[i] = wsrc[i];
    }
    // per-thread scale regs (cols fixed per thread across groups)
    const int srow = tid >> 2, sqc = (tid & 3) * 16;
    float4 sc4[4];
    #pragma unroll
    for (int i = 0; i < 4; i++) sc4[i] = *(const float4*)(scale + sqc + 4 * i);
    __syncthreads();

    const uint32_t* Wg = su;
    const uint32_t* Wv = su + 16384;
    const uint32_t* Wf = su + 32768;

    for (int g = 0; g < 8; g++) {
        const int row0 = blockIdx.x * 512 + g * 64;

        // ---- stage RMSNorm'd xn into scratch (fp32, stride 132) ----
        {
            const float4* xr = (const float4*)(x + ((size_t)b * NN + row0 + srow) * DD + sqc);
            float4 v[4];
            float ssq = 0.f;
            #pragma unroll
            for (int i = 0; i < 4; i++) {
                v[i] = xr[i];
                ssq += v[i].x * v[i].x + v[i].y * v[i].y + v[i].z * v[i].z + v[i].w * v[i].w;
            }
            ssq += __shfl_xor_sync(0xffffffffu, ssq, 1);
            ssq += __shfl_xor_sync(0xffffffffu, ssq, 2);
            const float rr = rsqrtf(ssq * (1.0f / 64.0f) + 1e-6f);
            #pragma unroll
            for (int i = 0; i < 4; i++) {
                float4 o = make_float4(v[i].x * rr * sc4[i].x, v[i].y * rr * sc4[i].y,
                                       v[i].z * rr * sc4[i].z, v[i].w * rr * sc4[i].w);
                *(float4*)&hs[srow * 132 + sqc + 4 * i] = o;
            }
        }
        __syncthreads();

        // ---- load xn A-fragments into registers (raw fp32 bits; HMMA truncates) ----
        uint32_t xa[8][4];
        #pragma unroll
        for (int t = 0; t < 8; t++) {
            xa[t][0] = __float_as_uint(hs[(m0 + r) * 132 + t * 8 + q]);
            xa[t][1] = __float_as_uint(hs[(m0 + r + 8) * 132 + t * 8 + q]);
            xa[t][2] = __float_as_uint(hs[(m0 + r) * 132 + t * 8 + q + 4]);
            xa[t][3] = __float_as_uint(hs[(m0 + r + 8) * 132 + t * 8 + q + 4]);
        }
        __syncthreads();   // scratch now free -> h buffer

        float oacc[8][4];
        #pragma unroll
        for (int i = 0; i < 8; i++) { oacc[i][0] = oacc[i][1] = oacc[i][2] = oacc[i][3] = 0.f; }

        #pragma unroll
        for (int ch = 0; ch < 2; ch++) {
            const int nb = hw * 128 + ch * 64;

            // ---- MMA1: gate/value [16 x 64] over k=64 ----
            float ga[8][4], va[8][4];
            #pragma unroll
            for (int i = 0; i < 8; i++) {
                ga[i][0] = ga[i][1] = ga[i][2] = ga[i][3] = 0.f;
                va[i][0] = va[i][1] = va[i][2] = va[i][3] = 0.f;
            }
            #pragma unroll
            for (int kt = 0; kt < 8; kt++) {
                const uint32_t* g0 = Wg + (kt * 8 + q) * 256;
                const uint32_t* v0 = Wv + (kt * 8 + q) * 256;
                #pragma unroll
                for (int nt = 0; nt < 8; nt++) {
                    const int c = ((nb + nt * 8) ^ q8) + r;
                    mma_tf32(ga[nt], xa[kt], g0[c], g0[c + 1024]);
                    mma_tf32(va[nt], xa[kt], v0[c], v0[c + 1024]);
                }
            }

            // ---- h = silu(gate) * value -> warp-private scratch (1 MUFU via tanh) ----
            #pragma unroll
            for (int nt = 0; nt < 8; nt++) {
                float h0 = 0.5f * ga[nt][0] * (1.f + tanha(0.5f * ga[nt][0])) * va[nt][0];
                float h1 = 0.5f * ga[nt][1] * (1.f + tanha(0.5f * ga[nt][1])) * va[nt][1];
                float h2 = 0.5f * ga[nt][2] * (1.f + tanha(0.5f * ga[nt][2])) * va[nt][2];
                float h3 = 0.5f * ga[nt][3] * (1.f + tanha(0.5f * ga[nt][3])) * va[nt][3];
                *(float2*)&hs[(m0 + r) * 132 + hoff + nt * 8 + 2 * q]     = make_float2(h0, h1);
                *(float2*)&hs[(m0 + r + 8) * 132 + hoff + nt * 8 + 2 * q] = make_float2(h2, h3);
            }
            __syncwarp();

            // ---- MMA2: out += h[16 x 64] @ fc2 ----
            #pragma unroll
            for (int kt = 0; kt < 8; kt++) {
                uint32_t ha[4];
                ha[0] = __float_as_uint(hs[(m0 + r) * 132 + hoff + kt * 8 + q]);
                ha[1] = __float_as_uint(hs[(m0 + r + 8) * 132 + hoff + kt * 8 + q]);
                ha[2] = __float_as_uint(hs[(m0 + r) * 132 + hoff + kt * 8 + q + 4]);
                ha[3] = __float_as_uint(hs[(m0 + r + 8) * 132 + hoff + kt * 8 + q + 4]);
                const int kk = nb + kt * 8 + q;
                const uint32_t* f0 = Wf + kk * 64;
                #pragma unroll
                for (int nt = 0; nt < 8; nt++) {
                    const int c = ((nt * 8) ^ q8) + r;
                    mma_tf32(oacc[nt], ha, f0[c], f0[c + 256]);
                }
            }
            __syncwarp();
        }
        __syncthreads();   // everyone done with h scratch

        // ---- stash out partials (plain layout per hw region) ----
        #pragma unroll
        for (int nt = 0; nt < 8; nt++) {
            *(float2*)&hs[(m0 + r) * 132 + hoff + nt * 8 + 2 * q]     = make_float2(oacc[nt][0], oacc[nt][1]);
            *(float2*)&hs[(m0 + r + 8) * 132 + hoff + nt * 8 + 2 * q] = make_float2(oacc[nt][2], oacc[nt][3]);
        }
        __syncthreads();

        // ---- reduce halves + residual + store ----
        {
            const float4* xr = (const float4*)(x + ((size_t)b * NN + row0 + srow) * DD + sqc);
            float* orow = out + ((size_t)b * NN + row0 + srow) * DD + sqc;
            #pragma unroll
            for (int i = 0; i < 4; i++) {
                float4 a  = *(const float4*)&hs[srow * 132 + sqc + 4 * i];
                float4 c  = *(const float4*)&hs[srow * 132 + 68 + sqc + 4 * i];
                float4 xv = xr[i];
                float4 o = make_float4(a.x + c.x + xv.x, a.y + c.y + xv.y,
                                       a.z + c.z + xv.z, a.w + c.w + xv.w);
                *(float4*)(orow + 4 * i) = o;
            }
        }
        __syncthreads();
    }
}

// ======================= launch =======================
extern "C" void kernel_launch(void* const* d_in, const int* in_sizes, int n_in,
                              void* d_out, int out_size) {
    const float* x     = (const float*)d_in[0];
    const float* s     = (const float*)d_in[1];
    const float* W     = (const float*)d_in[2];
    const float* bias  = (const float*)d_in[3];
    const float* scale = (const float*)d_in[4];
    float* out = (float*)d_out;

    cudaFuncSetAttribute(k1_mma, cudaFuncAttributeMaxDynamicSharedMemorySize, K1_SMEM);
    k1_mma<<<dim3(TOT / 128), 256, K1_SMEM>>>(s, W, bias);

    k2_normalize<<<dim3(BB), 256>>>();

    cudaFuncSetAttribute(k3_main, cudaFuncAttributeMaxDynamicSharedMemorySize, K3_SMEM);
    k3_main<<<dim3(8, BB), 256, K3_SMEM>>>(x, scale, out);
}